// round 1
// baseline (speedup 1.0000x reference)
#include <cuda_runtime.h>
#include <cstdint>

// Row layout: [x, y, w, h, obj_conf, cls_0 .. cls_79]  (85 floats per row)
// Outputs: detections [total,7] fp32, then valid [total] (fp32 1/0 or uint8).

#define ROW_LEN 85
#define NUM_CLS 80
#define CONF_THRES 0.05f

__global__ __launch_bounds__(256) void postproc_kernel(
    const float* __restrict__ pred,
    float* __restrict__ det,          // [total, 7]
    float* __restrict__ valid_f,      // [total] if float mode, else nullptr
    uint8_t* __restrict__ valid_b,    // [total] if bool mode, else nullptr
    int total)
{
    const int warp_id = (blockIdx.x * blockDim.x + threadIdx.x) >> 5;
    const int lane = threadIdx.x & 31;
    if (warp_id >= total) return;

    const float* row = pred + (long long)warp_id * ROW_LEN;

    // Coalesced row load: lanes cover elements [0,85)
    float v0 = row[lane];                       // elems 0..31
    float v1 = row[lane + 32];                  // elems 32..63
    float v2 = (lane < ROW_LEN - 64) ? row[lane + 64] : -1e30f;  // elems 64..84

    // Local max/argmax over class scores (element e -> class e-5), in
    // increasing class-index order so strict '>' keeps first occurrence.
    float m  = (lane >= 5) ? v0 : -1e30f;
    int   mi = lane - 5;
    int   i1 = lane + 27;                       // class of elem lane+32
    if (v1 > m) { m = v1; mi = i1; }
    int   i2 = lane + 59;                       // class of elem lane+64
    if (lane < ROW_LEN - 64 && v2 > m) { m = v2; mi = i2; }

    // Butterfly reduce (value max, lowest index on tie)
    #pragma unroll
    for (int off = 16; off > 0; off >>= 1) {
        float om = __shfl_xor_sync(0xFFFFFFFFu, m, off);
        int   oi = __shfl_xor_sync(0xFFFFFFFFu, mi, off);
        if (om > m || (om == m && oi < mi)) { m = om; mi = oi; }
    }

    // obj_conf is element 4 (lane 4's v0)
    float conf = __shfl_sync(0xFFFFFFFFu, v0, 4);
    bool  valid = (conf >= CONF_THRES);
    float vf = valid ? 1.0f : 0.0f;

    // Lanes 0..6 write the 7 detection values, lane 7 writes the mask.
    if (lane < 7) {
        float outv;
        if (lane < 5)      outv = v0 * vf;         // x,y,w,h,conf
        else if (lane == 5) outv = m * vf;         // class_conf
        else                outv = (float)mi * vf; // class_id
        det[(long long)warp_id * 7 + lane] = outv;
    } else if (lane == 7) {
        if (valid_f) valid_f[warp_id] = vf;
        else         valid_b[warp_id] = valid ? 1 : 0;
    }
}

extern "C" void kernel_launch(void* const* d_in, const int* in_sizes, int n_in,
                              void* d_out, int out_size)
{
    const float* pred = (const float*)d_in[0];
    const int total = in_sizes[0] / ROW_LEN;   // B*N rows

    float* det = (float*)d_out;
    float* valid_f = nullptr;
    uint8_t* valid_b = nullptr;
    if (out_size == total * 8) {
        // output dtype float32: detections [total*7] then valid [total] as 1.0/0.0
        valid_f = det + (long long)total * 7;
    } else {
        // valid stored as bytes after the detection floats
        valid_b = (uint8_t*)(det + (long long)total * 7);
    }

    const int warps_per_block = 8;              // 256 threads
    const int blocks = (total + warps_per_block - 1) / warps_per_block;
    postproc_kernel<<<blocks, 256>>>(pred, det, valid_f, valid_b, total);
}

// round 2
// speedup vs baseline: 1.6375x; 1.6375x over previous
#include <cuda_runtime.h>
#include <cstdint>

// Row layout: [x, y, w, h, obj_conf, cls_0 .. cls_79]  (85 floats per row)
// Outputs: detections [total,7] fp32, then valid [total] (fp32 1/0 or uint8).

#define ROW_LEN 85
#define CONF_THRES 0.05f

__global__ __launch_bounds__(256) void postproc_kernel(
    const float* __restrict__ pred,
    float* __restrict__ det,          // [total, 7]
    float* __restrict__ valid_f,      // [total] if float mode, else nullptr
    uint8_t* __restrict__ valid_b,    // [total] if bool mode, else nullptr
    int total)
{
    const int warp_id = (blockIdx.x * blockDim.x + threadIdx.x) >> 5;
    const int lane = threadIdx.x & 31;
    const int sub  = lane & 15;            // lane within half-warp (one row)
    const int half = lane >> 4;            // 0 or 1: which row of this warp

    const long long r = (long long)warp_id * 2 + half;
    if (r >= total) return;

    const float* row = pred + r * ROW_LEN;

    // 6 strided loads cover elements sub, sub+16, ..., sub+80 (85 total).
    // All accesses contiguous within each half-warp -> coalesced.
    float e0 = row[sub];
    float e1 = row[sub + 16];
    float e2 = row[sub + 32];
    float e3 = row[sub + 48];
    float e4 = row[sub + 64];
    float e5 = (sub < ROW_LEN - 80) ? row[sub + 80] : -1.0f;

    // Local max/argmax over class elements (element p -> class p-5),
    // processed in ascending class order so strict '>' keeps first occurrence.
    float m  = (sub >= 5) ? e0 : -1e30f;   // classes sub-5 (only sub>=5)
    unsigned mi = (unsigned)(sub - 5);
    if (e1 > m) { m = e1; mi = (unsigned)(sub + 11); }
    if (e2 > m) { m = e2; mi = (unsigned)(sub + 27); }
    if (e3 > m) { m = e3; mi = (unsigned)(sub + 43); }
    if (e4 > m) { m = e4; mi = (unsigned)(sub + 59); }
    if (sub < ROW_LEN - 80 && e5 > m) { m = e5; mi = (unsigned)(sub + 75); }

    // Warp-half reduction via redux.sync. All class scores are >= 0 (uniform
    // [0,1)), and every lane's final m comes from a real class element, so
    // float bit patterns are monotone as u32 -> exact max.
    const unsigned hmask = 0xFFFFu << (lane & 16);
    unsigned mb   = __float_as_uint(m);
    unsigned maxb = __reduce_max_sync(hmask, mb);
    unsigned cand = (mb == maxb) ? mi : 0xFFFFFFFFu;
    unsigned gidx = __reduce_min_sync(hmask, cand);   // first-occurrence argmax

    // obj_conf is element 4 of each row (held by sub==4 lane's e0).
    float conf  = __shfl_sync(0xFFFFFFFFu, e0, (lane & 16) | 4);
    bool  valid = (conf >= CONF_THRES);
    float vf    = valid ? 1.0f : 0.0f;

    // Lanes sub 0..6 write the 7 detection values; sub 7 writes the mask.
    if (sub < 7) {
        float outv;
        if (sub < 5)       outv = e0 * vf;                       // x,y,w,h,conf
        else if (sub == 5) outv = __uint_as_float(maxb) * vf;    // class_conf
        else               outv = (float)gidx * vf;              // class_id
        det[r * 7 + sub] = outv;
    } else if (sub == 7) {
        if (valid_f) valid_f[r] = vf;
        else         valid_b[r] = valid ? 1 : 0;
    }
}

extern "C" void kernel_launch(void* const* d_in, const int* in_sizes, int n_in,
                              void* d_out, int out_size)
{
    const float* pred = (const float*)d_in[0];
    const int total = in_sizes[0] / ROW_LEN;   // B*N rows

    float* det = (float*)d_out;
    float* valid_f = nullptr;
    uint8_t* valid_b = nullptr;
    if (out_size == total * 8) {
        valid_f = det + (long long)total * 7;      // valid as 1.0/0.0 floats
    } else {
        valid_b = (uint8_t*)(det + (long long)total * 7);  // valid as bytes
    }

    // 2 rows per warp, 8 warps per block -> 16 rows per block
    const int rows_per_block = 16;
    const int blocks = (total + rows_per_block - 1) / rows_per_block;
    postproc_kernel<<<blocks, 256>>>(pred, det, valid_f, valid_b, total);
}

// round 3
// speedup vs baseline: 2.0113x; 1.2282x over previous
#include <cuda_runtime.h>
#include <cstdint>

// Row layout: [x, y, w, h, obj_conf, cls_0 .. cls_79]  (85 floats per row)
// Outputs: detections [total,7] fp32, then valid [total] (fp32 1/0 or uint8).

#define ROW_LEN 85
#define CONF_THRES 0.05f

__global__ __launch_bounds__(256) void postproc_kernel(
    const float* __restrict__ pred,
    float* __restrict__ det,          // [total, 7]
    float* __restrict__ valid_f,      // [total] if float mode, else nullptr
    uint8_t* __restrict__ valid_b,    // [total] if bool mode, else nullptr
    int total)
{
    const int warp_id = (blockIdx.x * blockDim.x + threadIdx.x) >> 5;
    const int lane = threadIdx.x & 31;
    const int sub  = lane & 7;             // lane within 8-lane group (one row)
    const int grp  = lane >> 3;            // 0..3: which row of this warp

    const long long r = (long long)warp_id * 4 + grp;
    if (r >= total) return;

    const float* row = pred + r * ROW_LEN;

    // Each 8-lane group covers its row's 85 elements at stride 8:
    // elems sub, sub+8, ..., sub+80 (last only for sub<5).
    // Within a group the 8 loads are contiguous (full 32B sector per group).
    float e0 = row[sub];                              // elems 0..7
    float m  = (sub >= 5) ? e0 : -1e30f;              // classes 0..2 (sub 5..7)
    unsigned mi = (unsigned)(sub - 5);

    #pragma unroll
    for (int k = 1; k < 10; k++) {
        float v = row[sub + 8 * k];
        if (v > m) { m = v; mi = (unsigned)(sub + 8 * k - 5); }
    }
    if (sub < ROW_LEN - 80) {                         // elems 80..84
        float v = row[sub + 80];
        if (v > m) { m = v; mi = (unsigned)(sub + 75); }
    }

    // 8-lane group reduction via redux.sync (disjoint partition masks).
    // Class scores are uniform [0,1) -> non-negative -> u32-monotone bits.
    const unsigned gmask = 0xFFu << (lane & 24);
    unsigned mb   = __float_as_uint(m);
    unsigned maxb = __reduce_max_sync(gmask, mb);
    unsigned cand = (mb == maxb) ? mi : 0xFFFFFFFFu;
    unsigned gidx = __reduce_min_sync(gmask, cand);   // first-occurrence argmax

    // obj_conf is element 4 of each row (group lane sub==4 holds it in e0).
    float conf  = __shfl_sync(0xFFFFFFFFu, e0, (lane & 24) | 4);
    bool  valid = (conf >= CONF_THRES);
    float vf    = valid ? 1.0f : 0.0f;

    // Group lanes sub 0..6 write the 7 detection values; sub 7 writes the mask.
    if (sub < 7) {
        float outv;
        if (sub < 5)       outv = e0 * vf;                       // x,y,w,h,conf
        else if (sub == 5) outv = __uint_as_float(maxb) * vf;    // class_conf
        else               outv = (float)gidx * vf;              // class_id
        det[r * 7 + sub] = outv;
    } else {
        if (valid_f) valid_f[r] = vf;
        else         valid_b[r] = valid ? 1 : 0;
    }
}

extern "C" void kernel_launch(void* const* d_in, const int* in_sizes, int n_in,
                              void* d_out, int out_size)
{
    const float* pred = (const float*)d_in[0];
    const int total = in_sizes[0] / ROW_LEN;   // B*N rows

    float* det = (float*)d_out;
    float* valid_f = nullptr;
    uint8_t* valid_b = nullptr;
    if (out_size == total * 8) {
        valid_f = det + (long long)total * 7;      // valid as 1.0/0.0 floats
    } else {
        valid_b = (uint8_t*)(det + (long long)total * 7);  // valid as bytes
    }

    // 4 rows per warp, 8 warps per block -> 32 rows per block
    const int rows_per_block = 32;
    const int blocks = (total + rows_per_block - 1) / rows_per_block;
    postproc_kernel<<<blocks, 256>>>(pred, det, valid_f, valid_b, total);
}